// round 3
// baseline (speedup 1.0000x reference)
#include <cuda_runtime.h>
#include <math.h>

#define B_  4
#define S_  2048
#define D_  1024
#define H_  16
#define HD_ 64
#define M_  (B_ * S_)   // 8192

// Scratch for Q,K,V in [b,h,s,hd] layout (32 MB each)
__device__ float g_q[B_ * H_ * S_ * HD_];
__device__ float g_k[B_ * H_ * S_ * HD_];
__device__ float g_v[B_ * H_ * S_ * HD_];

// ---------------------------------------------------------------------------
// Kernel 1: fused QKV projection.  out = x @ W^T + b, written to [b,h,s,hd].
// Tile: BM=128, BN=64(==HD, one head per block col), BK=16. 256 thr, 8x4/thr.
// grid = (H_=16, M_/128=64, 3)   z selects (Wq|Wk|Wv)
// ---------------------------------------------------------------------------
__global__ __launch_bounds__(256) void qkv_kernel(
    const float* __restrict__ x,
    const float* __restrict__ Wq, const float* __restrict__ bq,
    const float* __restrict__ Wk, const float* __restrict__ bk,
    const float* __restrict__ Wv, const float* __restrict__ bv)
{
    constexpr int BM = 128, BK = 16, TM = 8, TN = 4;

    __shared__ float As[BK][BM + 4];   // [k][m], padded
    __shared__ float Bs[BK][64 + 4];   // [k][n], padded

    const int z = blockIdx.z;
    const float* W    = (z == 0) ? Wq : (z == 1) ? Wk : Wv;
    const float* bias = (z == 0) ? bq : (z == 1) ? bk : bv;
    float*       out  = (z == 0) ? g_q : (z == 1) ? g_k : g_v;

    const int tid = threadIdx.x;
    const int tx  = tid & 15;          // 0..15 -> col group
    const int ty  = tid >> 4;          // 0..15 -> row group
    const int row0 = ty * TM;
    const int col0 = tx * TN;
    const int rowBase = blockIdx.y * BM;
    const int h = blockIdx.x;          // head index == column-tile index

    float acc[TM][TN];
    #pragma unroll
    for (int i = 0; i < TM; ++i)
        #pragma unroll
        for (int j = 0; j < TN; ++j) acc[i][j] = 0.f;

    for (int kt = 0; kt < D_; kt += BK) {
        // Load A tile (128 x 16), transposed into As[k][m]
        #pragma unroll
        for (int i = 0; i < 2; ++i) {
            int idx = tid + i * 256;          // 0..511
            int r = idx >> 2;                 // 0..127
            int c = (idx & 3) << 2;           // 0,4,8,12
            float4 v = *reinterpret_cast<const float4*>(
                &x[(rowBase + r) * D_ + kt + c]);
            As[c + 0][r] = v.x; As[c + 1][r] = v.y;
            As[c + 2][r] = v.z; As[c + 3][r] = v.w;
        }
        // Load B tile: Bs[k][n] = W[h*64+n][kt+k]
        {
            int n = tid >> 2;                 // 0..63
            int c = (tid & 3) << 2;           // 0,4,8,12
            float4 v = *reinterpret_cast<const float4*>(
                &W[(h * 64 + n) * D_ + kt + c]);
            Bs[c + 0][n] = v.x; Bs[c + 1][n] = v.y;
            Bs[c + 2][n] = v.z; Bs[c + 3][n] = v.w;
        }
        __syncthreads();

        #pragma unroll
        for (int k = 0; k < BK; ++k) {
            float a[TM], b[TN];
            float4 a0 = *reinterpret_cast<const float4*>(&As[k][row0]);
            float4 a1 = *reinterpret_cast<const float4*>(&As[k][row0 + 4]);
            a[0] = a0.x; a[1] = a0.y; a[2] = a0.z; a[3] = a0.w;
            a[4] = a1.x; a[5] = a1.y; a[6] = a1.z; a[7] = a1.w;
            float4 b0 = *reinterpret_cast<const float4*>(&Bs[k][col0]);
            b[0] = b0.x; b[1] = b0.y; b[2] = b0.z; b[3] = b0.w;
            #pragma unroll
            for (int i = 0; i < TM; ++i)
                #pragma unroll
                for (int j = 0; j < TN; ++j)
                    acc[i][j] += a[i] * b[j];
        }
        __syncthreads();
    }

    // Epilogue: add bias, scatter to [b,h,s,hd]
    float bv4[TN];
    #pragma unroll
    for (int j = 0; j < TN; ++j) bv4[j] = bias[h * 64 + col0 + j];

    #pragma unroll
    for (int i = 0; i < TM; ++i) {
        int r = rowBase + row0 + i;
        int bb = r / S_;
        int ss = r - bb * S_;
        float4 o;
        o.x = acc[i][0] + bv4[0];
        o.y = acc[i][1] + bv4[1];
        o.z = acc[i][2] + bv4[2];
        o.w = acc[i][3] + bv4[3];
        *reinterpret_cast<float4*>(
            &out[((bb * H_ + h) * S_ + ss) * HD_ + col0]) = o;
    }
}

// ---------------------------------------------------------------------------
// Kernel 2: flash attention.  One block = 64 query rows of one (b,h).
// 256 threads as 16x16, each owning a 4x4 microtile. Online softmax with
// 16-lane shfl_xor row reductions. grid = (S_/64=32, B_*H_=64).
// Dynamic smem: Qs,Ks,Vs,Ps each [64][68] floats = 69632 B.
// ---------------------------------------------------------------------------
#define LDP 68   // padded row length

__global__ __launch_bounds__(256) void attn_kernel(float* __restrict__ out)
{
    extern __shared__ float sm[];
    float* Qs = sm;
    float* Ks = sm + 64 * LDP;
    float* Vs = sm + 2 * 64 * LDP;
    float* Ps = sm + 3 * 64 * LDP;

    const int tid = threadIdx.x;
    const int tx  = tid & 15;
    const int ty  = tid >> 4;
    const int row0 = ty * 4;
    const int col0 = tx * 4;

    const int qBase = blockIdx.x * 64;
    const int bh = blockIdx.y;
    const int b  = bh >> 4;
    const int h  = bh & 15;

    const float* qptr = g_q + (size_t)bh * S_ * HD_;
    const float* kptr = g_k + (size_t)bh * S_ * HD_;
    const float* vptr = g_v + (size_t)bh * S_ * HD_;

    // Load Q tile [64][64]
    #pragma unroll
    for (int i = 0; i < 4; ++i) {
        int idx = tid + i * 256;
        int r = idx >> 4;
        int c = (idx & 15) << 2;
        *reinterpret_cast<float4*>(&Qs[r * LDP + c]) =
            *reinterpret_cast<const float4*>(&qptr[(qBase + r) * HD_ + c]);
    }

    float m_i[4], l_i[4], o[4][4];
    #pragma unroll
    for (int i = 0; i < 4; ++i) {
        m_i[i] = -1e30f; l_i[i] = 0.f;
        #pragma unroll
        for (int j = 0; j < 4; ++j) o[i][j] = 0.f;
    }

    for (int kb = 0; kb < S_; kb += 64) {
        __syncthreads();   // protect Ks/Vs/Ps from previous iteration readers
        #pragma unroll
        for (int i = 0; i < 4; ++i) {
            int idx = tid + i * 256;
            int r = idx >> 4;
            int c = (idx & 15) << 2;
            *reinterpret_cast<float4*>(&Ks[r * LDP + c]) =
                *reinterpret_cast<const float4*>(&kptr[(kb + r) * HD_ + c]);
            *reinterpret_cast<float4*>(&Vs[r * LDP + c]) =
                *reinterpret_cast<const float4*>(&vptr[(kb + r) * HD_ + c]);
        }
        __syncthreads();

        // S = Q K^T (4x4 microtile, vectorized over d)
        float s[4][4];
        #pragma unroll
        for (int i = 0; i < 4; ++i)
            #pragma unroll
            for (int j = 0; j < 4; ++j) s[i][j] = 0.f;

        for (int d = 0; d < HD_; d += 4) {
            float qa[4][4], kf[4][4];
            #pragma unroll
            for (int i = 0; i < 4; ++i) {
                float4 t = *reinterpret_cast<const float4*>(&Qs[(row0 + i) * LDP + d]);
                qa[i][0] = t.x; qa[i][1] = t.y; qa[i][2] = t.z; qa[i][3] = t.w;
            }
            #pragma unroll
            for (int j = 0; j < 4; ++j) {
                float4 t = *reinterpret_cast<const float4*>(&Ks[(col0 + j) * LDP + d]);
                kf[j][0] = t.x; kf[j][1] = t.y; kf[j][2] = t.z; kf[j][3] = t.w;
            }
            #pragma unroll
            for (int i = 0; i < 4; ++i)
                #pragma unroll
                for (int j = 0; j < 4; ++j)
                    s[i][j] += qa[i][0] * kf[j][0] + qa[i][1] * kf[j][1]
                             + qa[i][2] * kf[j][2] + qa[i][3] * kf[j][3];
        }

        // Online softmax per query row (16 threads per row, shfl over tx)
        #pragma unroll
        for (int i = 0; i < 4; ++i) {
            #pragma unroll
            for (int j = 0; j < 4; ++j) s[i][j] *= 0.125f;   // 1/sqrt(64)
            float mt = fmaxf(fmaxf(s[i][0], s[i][1]), fmaxf(s[i][2], s[i][3]));
            #pragma unroll
            for (int off = 1; off < 16; off <<= 1)
                mt = fmaxf(mt, __shfl_xor_sync(0xffffffffu, mt, off));
            float mnew = fmaxf(m_i[i], mt);
            float corr = __expf(m_i[i] - mnew);
            float rs = 0.f;
            #pragma unroll
            for (int j = 0; j < 4; ++j) {
                s[i][j] = __expf(s[i][j] - mnew);
                rs += s[i][j];
            }
            #pragma unroll
            for (int off = 1; off < 16; off <<= 1)
                rs += __shfl_xor_sync(0xffffffffu, rs, off);
            l_i[i] = l_i[i] * corr + rs;
            m_i[i] = mnew;
            #pragma unroll
            for (int j = 0; j < 4; ++j) o[i][j] *= corr;
            *reinterpret_cast<float4*>(&Ps[(row0 + i) * LDP + col0]) =
                make_float4(s[i][0], s[i][1], s[i][2], s[i][3]);
        }
        __syncthreads();

        // O += P @ V
        for (int kk = 0; kk < 64; kk += 4) {
            float pr[4][4], vv[4][4];
            #pragma unroll
            for (int i = 0; i < 4; ++i) {
                float4 t = *reinterpret_cast<const float4*>(&Ps[(row0 + i) * LDP + kk]);
                pr[i][0] = t.x; pr[i][1] = t.y; pr[i][2] = t.z; pr[i][3] = t.w;
            }
            #pragma unroll
            for (int t4 = 0; t4 < 4; ++t4) {
                float4 t = *reinterpret_cast<const float4*>(&Vs[(kk + t4) * LDP + col0]);
                vv[t4][0] = t.x; vv[t4][1] = t.y; vv[t4][2] = t.z; vv[t4][3] = t.w;
            }
            #pragma unroll
            for (int i = 0; i < 4; ++i)
                #pragma unroll
                for (int j = 0; j < 4; ++j)
                    o[i][j] += pr[i][0] * vv[0][j] + pr[i][1] * vv[1][j]
                             + pr[i][2] * vv[2][j] + pr[i][3] * vv[3][j];
        }
    }

    // Epilogue: normalize and write [b,s,h*hd]
    #pragma unroll
    for (int i = 0; i < 4; ++i) {
        float inv = 1.f / l_i[i];
        int srow = qBase + row0 + i;
        float4 r;
        r.x = o[i][0] * inv; r.y = o[i][1] * inv;
        r.z = o[i][2] * inv; r.w = o[i][3] * inv;
        *reinterpret_cast<float4*>(
            &out[(b * S_ + srow) * D_ + h * HD_ + col0]) = r;
    }
}

// ---------------------------------------------------------------------------
extern "C" void kernel_launch(void* const* d_in, const int* in_sizes, int n_in,
                              void* d_out, int out_size)
{
    const float* x  = (const float*)d_in[0];
    const float* Wq = (const float*)d_in[1];
    const float* bq = (const float*)d_in[2];
    const float* Wk = (const float*)d_in[3];
    const float* bk = (const float*)d_in[4];
    const float* Wv = (const float*)d_in[5];
    const float* bv = (const float*)d_in[6];
    float* out = (float*)d_out;

    dim3 g1(H_, M_ / 128, 3);
    qkv_kernel<<<g1, 256>>>(x, Wq, bq, Wk, bk, Wv, bv);

    size_t smem = (size_t)4 * 64 * LDP * sizeof(float);   // 69632 B
    cudaFuncSetAttribute(attn_kernel,
                         cudaFuncAttributeMaxDynamicSharedMemorySize, (int)smem);
    attn_kernel<<<dim3(S_ / 64, B_ * H_), 256, smem>>>(out);
}

// round 4
// speedup vs baseline: 1.4987x; 1.4987x over previous
#include <cuda_runtime.h>
#include <math.h>

#define B_  4
#define S_  2048
#define D_  1024
#define H_  16
#define HD_ 64
#define M_  (B_ * S_)   // 8192

// Scratch for Q,K,V in [b,h,s,hd] layout (32 MB each)
__device__ float g_q[B_ * H_ * S_ * HD_];
__device__ float g_k[B_ * H_ * S_ * HD_];
__device__ float g_v[B_ * H_ * S_ * HD_];

// ---------------------------------------------------------------------------
// Kernel 1: fused QKV projection.  out = x @ W^T + b, written to [b,h,s,hd].
// Tile: BM=128, BN=128 (two heads), BK=16. 256 threads, 8x8 microtile.
// grid = (H_/2=8, M_/128=64, 3)   z selects (Wq|Wk|Wv)
// ---------------------------------------------------------------------------
__global__ __launch_bounds__(256) void qkv_kernel(
    const float* __restrict__ x,
    const float* __restrict__ Wq, const float* __restrict__ bq,
    const float* __restrict__ Wk, const float* __restrict__ bk,
    const float* __restrict__ Wv, const float* __restrict__ bv)
{
    constexpr int BM = 128, BN = 128, BK = 16;

    __shared__ float As[BK][BM + 4];   // [k][m]
    __shared__ float Bs[BK][BN + 4];   // [k][n]

    const int z = blockIdx.z;
    const float* W    = (z == 0) ? Wq : (z == 1) ? Wk : Wv;
    const float* bias = (z == 0) ? bq : (z == 1) ? bk : bv;
    float*       out  = (z == 0) ? g_q : (z == 1) ? g_k : g_v;

    const int tid = threadIdx.x;
    const int tx  = tid & 15;          // col group
    const int ty  = tid >> 4;          // row group
    const int row0 = ty * 8;
    const int col0 = tx * 8;
    const int rowBase = blockIdx.y * BM;
    const int hp = blockIdx.x;         // head-pair index

    float acc[8][8];
    #pragma unroll
    for (int i = 0; i < 8; ++i)
        #pragma unroll
        for (int j = 0; j < 8; ++j) acc[i][j] = 0.f;

    for (int kt = 0; kt < D_; kt += BK) {
        // A tile 128x16, transposed into As[k][m]
        #pragma unroll
        for (int i = 0; i < 2; ++i) {
            int idx = tid + i * 256;          // 0..511
            int r = idx >> 2;                 // 0..127
            int c = (idx & 3) << 2;           // 0,4,8,12
            float4 v = *reinterpret_cast<const float4*>(
                &x[(rowBase + r) * D_ + kt + c]);
            As[c + 0][r] = v.x; As[c + 1][r] = v.y;
            As[c + 2][r] = v.z; As[c + 3][r] = v.w;
        }
        // B tile 128x16: Bs[k][n] = W[hp*128+n][kt+k]
        #pragma unroll
        for (int i = 0; i < 2; ++i) {
            int idx = tid + i * 256;
            int n = idx >> 2;
            int c = (idx & 3) << 2;
            float4 v = *reinterpret_cast<const float4*>(
                &W[(hp * BN + n) * D_ + kt + c]);
            Bs[c + 0][n] = v.x; Bs[c + 1][n] = v.y;
            Bs[c + 2][n] = v.z; Bs[c + 3][n] = v.w;
        }
        __syncthreads();

        #pragma unroll
        for (int k = 0; k < BK; ++k) {
            float a[8], b[8];
            float4 a0 = *reinterpret_cast<const float4*>(&As[k][row0]);
            float4 a1 = *reinterpret_cast<const float4*>(&As[k][row0 + 4]);
            a[0]=a0.x; a[1]=a0.y; a[2]=a0.z; a[3]=a0.w;
            a[4]=a1.x; a[5]=a1.y; a[6]=a1.z; a[7]=a1.w;
            float4 b0 = *reinterpret_cast<const float4*>(&Bs[k][col0]);
            float4 b1 = *reinterpret_cast<const float4*>(&Bs[k][col0 + 4]);
            b[0]=b0.x; b[1]=b0.y; b[2]=b0.z; b[3]=b0.w;
            b[4]=b1.x; b[5]=b1.y; b[6]=b1.z; b[7]=b1.w;
            #pragma unroll
            for (int i = 0; i < 8; ++i)
                #pragma unroll
                for (int j = 0; j < 8; ++j)
                    acc[i][j] += a[i] * b[j];
        }
        __syncthreads();
    }

    // Epilogue: bias + scatter to [b,h,s,hd]. Thread's 8 cols stay in one head.
    const int gcol = hp * BN + col0;       // global projection column
    const int head = gcol >> 6;
    const int hd0  = gcol & 63;
    float bv8[8];
    #pragma unroll
    for (int j = 0; j < 8; ++j) bv8[j] = bias[gcol + j];

    #pragma unroll
    for (int i = 0; i < 8; ++i) {
        int r = rowBase + row0 + i;
        int bb = r >> 11;                  // / S_
        int ss = r & (S_ - 1);
        float* op = &out[(((size_t)bb * H_ + head) * S_ + ss) * HD_ + hd0];
        float4 o0, o1;
        o0.x = acc[i][0] + bv8[0]; o0.y = acc[i][1] + bv8[1];
        o0.z = acc[i][2] + bv8[2]; o0.w = acc[i][3] + bv8[3];
        o1.x = acc[i][4] + bv8[4]; o1.y = acc[i][5] + bv8[5];
        o1.z = acc[i][6] + bv8[6]; o1.w = acc[i][7] + bv8[7];
        *reinterpret_cast<float4*>(op)     = o0;
        *reinterpret_cast<float4*>(op + 4) = o1;
    }
}

// ---------------------------------------------------------------------------
// Kernel 2: flash attention.  One block = 128 query rows of one (b,h).
// 256 threads (16x16). QK^T: 8x8 microtile, outer-product over d using
// d-major Qt/Kt in smem (4 LDS.128 per 64 FFMA). PV: 8x4 microtile.
// grid = (S_/128=16, B_*H_=64).
// smem: Qt[64][132] + Kt[64][132] + Vs[128][68] + Ps[128][132] = 169984 B.
// ---------------------------------------------------------------------------
#define LQT 132   // Qt/Kt/Ps padded row length
#define LV  68    // Vs padded row length

__global__ __launch_bounds__(256) void attn_kernel(float* __restrict__ out)
{
    extern __shared__ float sm[];
    float* Qt = sm;                        // [64][LQT]  (d-major)
    float* Kt = sm + 64 * LQT;             // [64][LQT]  (d-major)
    float* Vs = sm + 2 * 64 * LQT;         // [128][LV]  (key-major)
    float* Ps = Vs + 128 * LV;             // [128][LQT] (query-major)

    const int tid = threadIdx.x;
    const int tx  = tid & 15;
    const int ty  = tid >> 4;
    const int row0  = ty * 8;              // query rows (both phases)
    const int col0s = tx * 8;              // S columns (QK phase)
    const int col0o = tx * 4;              // O columns (PV phase)

    const int qBase = blockIdx.x * 128;
    const int bh = blockIdx.y;
    const int b  = bh >> 4;
    const int h  = bh & 15;

    const float* qptr = g_q + (size_t)bh * S_ * HD_;
    const float* kptr = g_k + (size_t)bh * S_ * HD_;
    const float* vptr = g_v + (size_t)bh * S_ * HD_;

    // Load Q tile [128][64] -> Qt[d][m], scale 1/sqrt(64) folded in.
    #pragma unroll
    for (int i = 0; i < 8; ++i) {
        int idx = tid + i * 256;           // 0..2047
        int r = idx >> 4;                  // 0..127
        int c = (idx & 15) << 2;           // 0..60
        float4 v = *reinterpret_cast<const float4*>(
            &qptr[(qBase + r) * HD_ + c]);
        Qt[(c + 0) * LQT + r] = v.x * 0.125f;
        Qt[(c + 1) * LQT + r] = v.y * 0.125f;
        Qt[(c + 2) * LQT + r] = v.z * 0.125f;
        Qt[(c + 3) * LQT + r] = v.w * 0.125f;
    }

    float m_i[8], l_i[8], o[8][4];
    #pragma unroll
    for (int i = 0; i < 8; ++i) {
        m_i[i] = -1e30f; l_i[i] = 0.f;
        #pragma unroll
        for (int j = 0; j < 4; ++j) o[i][j] = 0.f;
    }

    for (int kb = 0; kb < S_; kb += 128) {
        __syncthreads();   // previous iteration's PV reads done
        // Load K tile -> Kt[d][n] (transposed), V tile -> Vs[k][d] (natural)
        #pragma unroll
        for (int i = 0; i < 8; ++i) {
            int idx = tid + i * 256;
            int r = idx >> 4;
            int c = (idx & 15) << 2;
            float4 kv = *reinterpret_cast<const float4*>(
                &kptr[(kb + r) * HD_ + c]);
            Kt[(c + 0) * LQT + r] = kv.x;
            Kt[(c + 1) * LQT + r] = kv.y;
            Kt[(c + 2) * LQT + r] = kv.z;
            Kt[(c + 3) * LQT + r] = kv.w;
            *reinterpret_cast<float4*>(&Vs[r * LV + c]) =
                *reinterpret_cast<const float4*>(&vptr[(kb + r) * HD_ + c]);
        }
        __syncthreads();

        // S = Q K^T : outer product over d, 8x8 microtile
        float s[8][8];
        #pragma unroll
        for (int i = 0; i < 8; ++i)
            #pragma unroll
            for (int j = 0; j < 8; ++j) s[i][j] = 0.f;

        #pragma unroll 4
        for (int d = 0; d < HD_; ++d) {
            float a[8], bb8[8];
            float4 a0 = *reinterpret_cast<const float4*>(&Qt[d * LQT + row0]);
            float4 a1 = *reinterpret_cast<const float4*>(&Qt[d * LQT + row0 + 4]);
            a[0]=a0.x; a[1]=a0.y; a[2]=a0.z; a[3]=a0.w;
            a[4]=a1.x; a[5]=a1.y; a[6]=a1.z; a[7]=a1.w;
            float4 b0 = *reinterpret_cast<const float4*>(&Kt[d * LQT + col0s]);
            float4 b1 = *reinterpret_cast<const float4*>(&Kt[d * LQT + col0s + 4]);
            bb8[0]=b0.x; bb8[1]=b0.y; bb8[2]=b0.z; bb8[3]=b0.w;
            bb8[4]=b1.x; bb8[5]=b1.y; bb8[6]=b1.z; bb8[7]=b1.w;
            #pragma unroll
            for (int i = 0; i < 8; ++i)
                #pragma unroll
                for (int j = 0; j < 8; ++j)
                    s[i][j] += a[i] * bb8[j];
        }

        // Online softmax per query row (16 threads/row, shfl over tx bits)
        #pragma unroll
        for (int i = 0; i < 8; ++i) {
            float mt = s[i][0];
            #pragma unroll
            for (int j = 1; j < 8; ++j) mt = fmaxf(mt, s[i][j]);
            #pragma unroll
            for (int off = 1; off < 16; off <<= 1)
                mt = fmaxf(mt, __shfl_xor_sync(0xffffffffu, mt, off));
            float mnew = fmaxf(m_i[i], mt);
            float corr = __expf(m_i[i] - mnew);
            float rs = 0.f;
            #pragma unroll
            for (int j = 0; j < 8; ++j) {
                s[i][j] = __expf(s[i][j] - mnew);
                rs += s[i][j];
            }
            #pragma unroll
            for (int off = 1; off < 16; off <<= 1)
                rs += __shfl_xor_sync(0xffffffffu, rs, off);
            l_i[i] = l_i[i] * corr + rs;
            m_i[i] = mnew;
            #pragma unroll
            for (int j = 0; j < 4; ++j) o[i][j] *= corr;
            *reinterpret_cast<float4*>(&Ps[(row0 + i) * LQT + col0s]) =
                make_float4(s[i][0], s[i][1], s[i][2], s[i][3]);
            *reinterpret_cast<float4*>(&Ps[(row0 + i) * LQT + col0s + 4]) =
                make_float4(s[i][4], s[i][5], s[i][6], s[i][7]);
        }
        __syncthreads();

        // O += P @ V   (8 rows x 4 cols per thread)
        #pragma unroll 8
        for (int kk = 0; kk < 128; kk += 4) {
            float4 pr[8];
            #pragma unroll
            for (int i = 0; i < 8; ++i)
                pr[i] = *reinterpret_cast<const float4*>(
                    &Ps[(row0 + i) * LQT + kk]);
            float4 v0 = *reinterpret_cast<const float4*>(&Vs[(kk + 0) * LV + col0o]);
            float4 v1 = *reinterpret_cast<const float4*>(&Vs[(kk + 1) * LV + col0o]);
            float4 v2 = *reinterpret_cast<const float4*>(&Vs[(kk + 2) * LV + col0o]);
            float4 v3 = *reinterpret_cast<const float4*>(&Vs[(kk + 3) * LV + col0o]);
            #pragma unroll
            for (int i = 0; i < 8; ++i) {
                o[i][0] += pr[i].x * v0.x + pr[i].y * v1.x + pr[i].z * v2.x + pr[i].w * v3.x;
                o[i][1] += pr[i].x * v0.y + pr[i].y * v1.y + pr[i].z * v2.y + pr[i].w * v3.y;
                o[i][2] += pr[i].x * v0.z + pr[i].y * v1.z + pr[i].z * v2.z + pr[i].w * v3.z;
                o[i][3] += pr[i].x * v0.w + pr[i].y * v1.w + pr[i].z * v2.w + pr[i].w * v3.w;
            }
        }
    }

    // Epilogue: normalize, write [b,s,h*hd]
    #pragma unroll
    for (int i = 0; i < 8; ++i) {
        float inv = 1.f / l_i[i];
        int srow = qBase + row0 + i;
        float4 r;
        r.x = o[i][0] * inv; r.y = o[i][1] * inv;
        r.z = o[i][2] * inv; r.w = o[i][3] * inv;
        *reinterpret_cast<float4*>(
            &out[((size_t)(b * S_ + srow)) * D_ + h * HD_ + col0o]) = r;
    }
}

// ---------------------------------------------------------------------------
extern "C" void kernel_launch(void* const* d_in, const int* in_sizes, int n_in,
                              void* d_out, int out_size)
{
    const float* x  = (const float*)d_in[0];
    const float* Wq = (const float*)d_in[1];
    const float* bq = (const float*)d_in[2];
    const float* Wk = (const float*)d_in[3];
    const float* bk = (const float*)d_in[4];
    const float* Wv = (const float*)d_in[5];
    const float* bv = (const float*)d_in[6];
    float* out = (float*)d_out;

    dim3 g1(H_ / 2, M_ / 128, 3);
    qkv_kernel<<<g1, 256>>>(x, Wq, bq, Wk, bk, Wv, bv);

    size_t smem = (size_t)(2 * 64 * LQT + 128 * LV + 128 * LQT) * sizeof(float); // 169984
    cudaFuncSetAttribute(attn_kernel,
                         cudaFuncAttributeMaxDynamicSharedMemorySize, (int)smem);
    attn_kernel<<<dim3(S_ / 128, B_ * H_), 256, smem>>>(out);
}

// round 8
// speedup vs baseline: 3.2437x; 2.1643x over previous
#include <cuda_runtime.h>
#include <cstdint>
#include <math.h>

#define B_  4
#define S_  2048
#define D_  1024
#define H_  16
#define HD_ 64
#define M_  (B_ * S_)   // 8192

// Scratch for Q,K,V in [b,h,s,hd] layout (32 MB each)
__device__ float g_q[B_ * H_ * S_ * HD_];
__device__ float g_k[B_ * H_ * S_ * HD_];
__device__ float g_v[B_ * H_ * S_ * HD_];

// ---------------------------------------------------------------------------
// tf32 warp MMA helpers (portable PTX, works on compute_103)
// ---------------------------------------------------------------------------
__device__ __forceinline__ uint32_t f2tf32(float x) {
    uint32_t r;
    asm("cvt.rna.tf32.f32 %0, %1;" : "=r"(r) : "f"(x));
    return r;
}
__device__ __forceinline__ void mma_tf32(float d[4], const uint32_t a[4],
                                         const uint32_t b[2], const float c[4]) {
    asm volatile(
        "mma.sync.aligned.m16n8k8.row.col.f32.tf32.tf32.f32 "
        "{%0,%1,%2,%3}, {%4,%5,%6,%7}, {%8,%9}, {%10,%11,%12,%13};"
        : "=f"(d[0]), "=f"(d[1]), "=f"(d[2]), "=f"(d[3])
        : "r"(a[0]), "r"(a[1]), "r"(a[2]), "r"(a[3]),
          "r"(b[0]), "r"(b[1]),
          "f"(c[0]), "f"(c[1]), "f"(c[2]), "f"(c[3]));
}

// ===========================================================================
// Kernel 1: QKV projection via tf32 mma.sync.
// CTA tile 128x128, BK=64, 256 threads = 8 warps (4x2), warp tile 32x64.
// grid = (24, 64): bx>>3 = (q|k|v), (bx&7)*128 = n0, by*128 = m0.
// smem: As[128][68] + Bs[128][68] tf32  (69632 B)
// ===========================================================================
#define QKV_LA 68
#define QKV_SMEM ((size_t)2 * 128 * QKV_LA * 4)

__global__ __launch_bounds__(256) void qkv_mma_kernel(
    const float* __restrict__ x,
    const float* __restrict__ Wq, const float* __restrict__ bq,
    const float* __restrict__ Wk, const float* __restrict__ bk,
    const float* __restrict__ Wv, const float* __restrict__ bv)
{
    extern __shared__ uint32_t smq[];
    uint32_t* As = smq;                      // [128][68]  rows=m, cols=k
    uint32_t* Bs = smq + 128 * QKV_LA;       // [128][68]  rows=n, cols=k

    const int tid  = threadIdx.x;
    const int wid  = tid >> 5;
    const int lane = tid & 31;
    const int qr = lane >> 2;                // quad row 0..7
    const int qc = lane & 3;                 // quad col 0..3

    const int bx = blockIdx.x;
    const int z  = bx >> 3;
    const int n0 = (bx & 7) * 128;
    const int m0 = blockIdx.y * 128;

    const float* W    = (z == 0) ? Wq : (z == 1) ? Wk : Wv;
    const float* bias = (z == 0) ? bq : (z == 1) ? bk : bv;
    float*       out  = (z == 0) ? g_q : (z == 1) ? g_k : g_v;

    const int warpM = (wid >> 1) * 32;       // 0,32,64,96
    const int warpN = (wid & 1) * 64;        // 0,64

    float acc[2][8][4];
    #pragma unroll
    for (int mt = 0; mt < 2; ++mt)
        #pragma unroll
        for (int nt = 0; nt < 8; ++nt)
            #pragma unroll
            for (int i = 0; i < 4; ++i) acc[mt][nt][i] = 0.f;

    for (int kc = 0; kc < D_; kc += 64) {
        __syncthreads();
        // stage A (x rows m0..m0+127, cols kc..kc+63) and B (W rows n0..)
        #pragma unroll
        for (int i = 0; i < 8; ++i) {
            int idx = tid + i * 256;         // 0..2047
            int r = idx >> 4;                // 0..127
            int c = (idx & 15) << 2;         // 0..60
            float4 va = *reinterpret_cast<const float4*>(&x[(size_t)(m0 + r) * D_ + kc + c]);
            uint4 ta = make_uint4(f2tf32(va.x), f2tf32(va.y), f2tf32(va.z), f2tf32(va.w));
            *reinterpret_cast<uint4*>(&As[r * QKV_LA + c]) = ta;
            float4 vb = *reinterpret_cast<const float4*>(&W[(size_t)(n0 + r) * D_ + kc + c]);
            uint4 tb = make_uint4(f2tf32(vb.x), f2tf32(vb.y), f2tf32(vb.z), f2tf32(vb.w));
            *reinterpret_cast<uint4*>(&Bs[r * QKV_LA + c]) = tb;
        }
        __syncthreads();

        #pragma unroll 2
        for (int k8 = 0; k8 < 8; ++k8) {
            int k0 = k8 * 8;
            uint32_t a[2][4];
            #pragma unroll
            for (int mt = 0; mt < 2; ++mt) {
                int r = warpM + mt * 16 + qr;
                a[mt][0] = As[r * QKV_LA + k0 + qc];
                a[mt][1] = As[(r + 8) * QKV_LA + k0 + qc];
                a[mt][2] = As[r * QKV_LA + k0 + qc + 4];
                a[mt][3] = As[(r + 8) * QKV_LA + k0 + qc + 4];
            }
            #pragma unroll
            for (int nt = 0; nt < 8; ++nt) {
                uint32_t b[2];
                int n = warpN + nt * 8 + qr;
                b[0] = Bs[n * QKV_LA + k0 + qc];
                b[1] = Bs[n * QKV_LA + k0 + qc + 4];
                mma_tf32(acc[0][nt], a[0], b, acc[0][nt]);
                mma_tf32(acc[1][nt], a[1], b, acc[1][nt]);
            }
        }
    }

    // Epilogue: bias + scatter to [b,h,s,hd]
    #pragma unroll
    for (int mt = 0; mt < 2; ++mt) {
        #pragma unroll
        for (int nt = 0; nt < 8; ++nt) {
            int gn = n0 + warpN + nt * 8 + 2 * qc;   // even
            int head = gn >> 6;
            int hd = gn & 63;
            float b0 = bias[gn], b1 = bias[gn + 1];
            int rA = m0 + warpM + mt * 16 + qr;
            int rB = rA + 8;
            int bbA = rA >> 11, ssA = rA & (S_ - 1);
            int bbB = rB >> 11, ssB = rB & (S_ - 1);
            float2 vA = make_float2(acc[mt][nt][0] + b0, acc[mt][nt][1] + b1);
            float2 vB = make_float2(acc[mt][nt][2] + b0, acc[mt][nt][3] + b1);
            *reinterpret_cast<float2*>(
                &out[(((size_t)bbA * H_ + head) * S_ + ssA) * HD_ + hd]) = vA;
            *reinterpret_cast<float2*>(
                &out[(((size_t)bbB * H_ + head) * S_ + ssB) * HD_ + hd]) = vB;
        }
    }
}

// ===========================================================================
// Kernel 2: flash attention via tf32 mma.sync.
// Block = 128 q-rows of one (b,h); 256 threads = 8 warps; warp w owns q-rows
// [w*16, w*16+16). Key chunks of 128. Online softmax on C fragments.
// smem (uint32/tf32): Qs[128][68] Ks[128][68] Vs[128][72] Ps[128][132]
//   = 128*340*4 = 174080 B
// ===========================================================================
#define LQ 68
#define LK 68
#define LVV 72
#define LP 132
#define ATT_SMEM ((size_t)128 * (LQ + LK + LVV + LP) * 4)

__global__ __launch_bounds__(256) void attn_kernel(float* __restrict__ out)
{
    extern __shared__ uint32_t sma[];
    uint32_t* Qs = sma;                       // [128][LQ]  q-major (pre-scaled)
    uint32_t* Ks = Qs + 128 * LQ;             // [128][LK]  key-major
    uint32_t* Vs = Ks + 128 * LK;             // [128][LVV] key-major
    uint32_t* Ps = Vs + 128 * LVV;            // [128][LP]  q-major

    const int tid  = threadIdx.x;
    const int wid  = tid >> 5;
    const int lane = tid & 31;
    const int qr = lane >> 2;
    const int qc = lane & 3;
    const int wq = wid * 16;                  // warp's q-row base

    const int qBase = blockIdx.x * 128;
    const int bh = blockIdx.y;
    const int b  = bh >> 4;
    const int h  = bh & 15;

    const float* qptr = g_q + (size_t)bh * S_ * HD_;
    const float* kptr = g_k + (size_t)bh * S_ * HD_;
    const float* vptr = g_v + (size_t)bh * S_ * HD_;

    // Load Q tile [128][64], scale 1/sqrt(64), convert tf32
    #pragma unroll
    for (int i = 0; i < 2; ++i) {
        int idx = tid + i * 256;              // 0..511
        int r = idx >> 2;                     // 0..127
        int c = (idx & 3) << 4;               // 0,16,32,48
        #pragma unroll
        for (int u = 0; u < 4; ++u) {
            float4 v = *reinterpret_cast<const float4*>(
                &qptr[(size_t)(qBase + r) * HD_ + c + u * 4]);
            uint4 t = make_uint4(f2tf32(v.x * 0.125f), f2tf32(v.y * 0.125f),
                                 f2tf32(v.z * 0.125f), f2tf32(v.w * 0.125f));
            *reinterpret_cast<uint4*>(&Qs[r * LQ + c + u * 4]) = t;
        }
    }

    float o[8][4];
    #pragma unroll
    for (int nt = 0; nt < 8; ++nt)
        #pragma unroll
        for (int i = 0; i < 4; ++i) o[nt][i] = 0.f;
    float mA = -1e30f, mB = -1e30f, lA = 0.f, lB = 0.f;

    for (int kb = 0; kb < S_; kb += 128) {
        __syncthreads();   // prior PV reads of Vs / stores to Ps complete
        // Load K and V chunks (tf32)
        #pragma unroll
        for (int i = 0; i < 2; ++i) {
            int idx = tid + i * 256;
            int r = idx >> 2;
            int c = (idx & 3) << 4;
            #pragma unroll
            for (int u = 0; u < 4; ++u) {
                float4 kv = *reinterpret_cast<const float4*>(
                    &kptr[(size_t)(kb + r) * HD_ + c + u * 4]);
                uint4 tk = make_uint4(f2tf32(kv.x), f2tf32(kv.y),
                                      f2tf32(kv.z), f2tf32(kv.w));
                *reinterpret_cast<uint4*>(&Ks[r * LK + c + u * 4]) = tk;
                float4 vv = *reinterpret_cast<const float4*>(
                    &vptr[(size_t)(kb + r) * HD_ + c + u * 4]);
                uint4 tv = make_uint4(f2tf32(vv.x), f2tf32(vv.y),
                                      f2tf32(vv.z), f2tf32(vv.w));
                *reinterpret_cast<uint4*>(&Vs[r * LVV + c + u * 4]) = tv;
            }
        }
        __syncthreads();

        // S = Q K^T : 1 m-tile x 16 n-tiles per warp, k = 64 (8 steps)
        float s[16][4];
        #pragma unroll
        for (int nt = 0; nt < 16; ++nt)
            #pragma unroll
            for (int i = 0; i < 4; ++i) s[nt][i] = 0.f;

        #pragma unroll 2
        for (int k8 = 0; k8 < 8; ++k8) {
            int k0 = k8 * 8;
            uint32_t a[4];
            a[0] = Qs[(wq + qr) * LQ + k0 + qc];
            a[1] = Qs[(wq + qr + 8) * LQ + k0 + qc];
            a[2] = Qs[(wq + qr) * LQ + k0 + qc + 4];
            a[3] = Qs[(wq + qr + 8) * LQ + k0 + qc + 4];
            #pragma unroll
            for (int nt = 0; nt < 16; ++nt) {
                uint32_t bfr[2];
                bfr[0] = Ks[(nt * 8 + qr) * LK + k0 + qc];
                bfr[1] = Ks[(nt * 8 + qr) * LK + k0 + qc + 4];
                mma_tf32(s[nt], a, bfr, s[nt]);
            }
        }

        // Online softmax on fragments.
        // Row A = wq+qr (regs 0,1), Row B = wq+qr+8 (regs 2,3); cols spread
        // over quad lanes -> reduce in-thread over nt, then shfl 1,2.
        float mtA = -1e30f, mtB = -1e30f;
        #pragma unroll
        for (int nt = 0; nt < 16; ++nt) {
            mtA = fmaxf(mtA, fmaxf(s[nt][0], s[nt][1]));
            mtB = fmaxf(mtB, fmaxf(s[nt][2], s[nt][3]));
        }
        #pragma unroll
        for (int off = 1; off < 4; off <<= 1) {
            mtA = fmaxf(mtA, __shfl_xor_sync(0xffffffffu, mtA, off));
            mtB = fmaxf(mtB, __shfl_xor_sync(0xffffffffu, mtB, off));
        }
        float mnA = fmaxf(mA, mtA), mnB = fmaxf(mB, mtB);
        float cA = __expf(mA - mnA), cB = __expf(mB - mnB);
        float rsA = 0.f, rsB = 0.f;
        #pragma unroll
        for (int nt = 0; nt < 16; ++nt) {
            s[nt][0] = __expf(s[nt][0] - mnA);
            s[nt][1] = __expf(s[nt][1] - mnA);
            s[nt][2] = __expf(s[nt][2] - mnB);
            s[nt][3] = __expf(s[nt][3] - mnB);
            rsA += s[nt][0] + s[nt][1];
            rsB += s[nt][2] + s[nt][3];
        }
        #pragma unroll
        for (int off = 1; off < 4; off <<= 1) {
            rsA += __shfl_xor_sync(0xffffffffu, rsA, off);
            rsB += __shfl_xor_sync(0xffffffffu, rsB, off);
        }
        lA = lA * cA + rsA;  mA = mnA;
        lB = lB * cB + rsB;  mB = mnB;
        #pragma unroll
        for (int nt = 0; nt < 8; ++nt) {
            o[nt][0] *= cA; o[nt][1] *= cA;
            o[nt][2] *= cB; o[nt][3] *= cB;
        }

        // Store P (tf32) to smem for the PV A-operand
        #pragma unroll
        for (int nt = 0; nt < 16; ++nt) {
            uint2 pa = make_uint2(f2tf32(s[nt][0]), f2tf32(s[nt][1]));
            uint2 pb = make_uint2(f2tf32(s[nt][2]), f2tf32(s[nt][3]));
            *reinterpret_cast<uint2*>(&Ps[(wq + qr) * LP + nt * 8 + 2 * qc]) = pa;
            *reinterpret_cast<uint2*>(&Ps[(wq + qr + 8) * LP + nt * 8 + 2 * qc]) = pb;
        }
        __syncwarp();   // warp writes/reads its own 16 Ps rows only

        // O += P V : 1 m-tile x 8 n-tiles, k = 128 (16 steps)
        #pragma unroll 4
        for (int k8 = 0; k8 < 16; ++k8) {
            int k0 = k8 * 8;
            uint32_t a[4];
            a[0] = Ps[(wq + qr) * LP + k0 + qc];
            a[1] = Ps[(wq + qr + 8) * LP + k0 + qc];
            a[2] = Ps[(wq + qr) * LP + k0 + qc + 4];
            a[3] = Ps[(wq + qr + 8) * LP + k0 + qc + 4];
            #pragma unroll
            for (int nt = 0; nt < 8; ++nt) {
                uint32_t bfr[2];
                bfr[0] = Vs[(k0 + qc) * LVV + nt * 8 + qr];
                bfr[1] = Vs[(k0 + qc + 4) * LVV + nt * 8 + qr];
                mma_tf32(o[nt], a, bfr, o[nt]);
            }
        }
    }

    // Epilogue: normalize, write [b,s,h*hd]
    float invA = 1.f / lA, invB = 1.f / lB;
    int rowA = qBase + wq + qr;
    int rowB = rowA + 8;
    #pragma unroll
    for (int nt = 0; nt < 8; ++nt) {
        int col = h * HD_ + nt * 8 + 2 * qc;
        float2 vA = make_float2(o[nt][0] * invA, o[nt][1] * invA);
        float2 vB = make_float2(o[nt][2] * invB, o[nt][3] * invB);
        *reinterpret_cast<float2*>(&out[(size_t)(b * S_ + rowA) * D_ + col]) = vA;
        *reinterpret_cast<float2*>(&out[(size_t)(b * S_ + rowB) * D_ + col]) = vB;
    }
}

// ---------------------------------------------------------------------------
extern "C" void kernel_launch(void* const* d_in, const int* in_sizes, int n_in,
                              void* d_out, int out_size)
{
    const float* x  = (const float*)d_in[0];
    const float* Wq = (const float*)d_in[1];
    const float* bq = (const float*)d_in[2];
    const float* Wk = (const float*)d_in[3];
    const float* bk = (const float*)d_in[4];
    const float* Wv = (const float*)d_in[5];
    const float* bv = (const float*)d_in[6];
    float* out = (float*)d_out;

    cudaFuncSetAttribute(qkv_mma_kernel,
                         cudaFuncAttributeMaxDynamicSharedMemorySize, (int)QKV_SMEM);
    qkv_mma_kernel<<<dim3(24, 64), 256, QKV_SMEM>>>(x, Wq, bq, Wk, bk, Wv, bv);

    cudaFuncSetAttribute(attn_kernel,
                         cudaFuncAttributeMaxDynamicSharedMemorySize, (int)ATT_SMEM);
    attn_kernel<<<dim3(S_ / 128, B_ * H_), 256, ATT_SMEM>>>(out);
}

// round 10
// speedup vs baseline: 4.4787x; 1.3807x over previous
#include <cuda_runtime.h>
#include <cstdint>
#include <math.h>

#define B_  4
#define S_  2048
#define D_  1024
#define H_  16
#define HD_ 64
#define M_  (B_ * S_)   // 8192

// Scratch for Q,K,V in [b,h,s,hd] layout (32 MB each)
__device__ float g_q[B_ * H_ * S_ * HD_];
__device__ float g_k[B_ * H_ * S_ * HD_];
__device__ float g_v[B_ * H_ * S_ * HD_];

// ---------------------------------------------------------------------------
// tf32 warp MMA helpers (portable PTX, works on compute_103)
// ---------------------------------------------------------------------------
__device__ __forceinline__ uint32_t f2tf32(float x) {
    uint32_t r;
    asm("cvt.rna.tf32.f32 %0, %1;" : "=r"(r) : "f"(x));
    return r;
}
__device__ __forceinline__ void mma_tf32(float d[4], const uint32_t a[4],
                                         const uint32_t b[2], const float c[4]) {
    asm volatile(
        "mma.sync.aligned.m16n8k8.row.col.f32.tf32.tf32.f32 "
        "{%0,%1,%2,%3}, {%4,%5,%6,%7}, {%8,%9}, {%10,%11,%12,%13};"
        : "=f"(d[0]), "=f"(d[1]), "=f"(d[2]), "=f"(d[3])
        : "r"(a[0]), "r"(a[1]), "r"(a[2]), "r"(a[3]),
          "r"(b[0]), "r"(b[1]),
          "f"(c[0]), "f"(c[1]), "f"(c[2]), "f"(c[3]));
}

// ===========================================================================
// Kernel 1: QKV projection via tf32 mma.sync, double-buffered (as R8).
// CTA tile 128x128, BK=32 (32 chunks), 256 threads = 8 warps (4x2),
// warp tile 32x64. Register prefetch overlaps gmem loads with MMA compute.
// grid = (24, 64): bx>>3 = (q|k|v), (bx&7)*128 = n0, by*128 = m0.
// smem: 2 stages x (As[128][36] + Bs[128][36]) tf32 = 73728 B
// ===========================================================================
#define QLA 36
#define QSTG (2 * 128 * QLA)
#define QKV_SMEM ((size_t)2 * QSTG * 4)

__global__ __launch_bounds__(256, 2) void qkv_mma_kernel(
    const float* __restrict__ x,
    const float* __restrict__ Wq, const float* __restrict__ bq,
    const float* __restrict__ Wk, const float* __restrict__ bk,
    const float* __restrict__ Wv, const float* __restrict__ bv)
{
    extern __shared__ uint32_t smq[];

    const int tid  = threadIdx.x;
    const int lane = tid & 31;
    const int wid  = tid >> 5;
    const int qr = lane >> 2;
    const int qc = lane & 3;

    const int bx = blockIdx.x;
    const int z  = bx >> 3;
    const int n0 = (bx & 7) * 128;
    const int m0 = blockIdx.y * 128;

    const float* W    = (z == 0) ? Wq : (z == 1) ? Wk : Wv;
    const float* bias = (z == 0) ? bq : (z == 1) ? bk : bv;
    float*       out  = (z == 0) ? g_q : (z == 1) ? g_k : g_v;

    const int warpM = (wid >> 1) * 32;       // 0,32,64,96
    const int warpN = (wid & 1) * 64;        // 0,64

    const int lr = tid >> 3;                 // loader row 0..31 (x4 via i)
    const int lc = (tid & 7) << 2;           // loader col 0,4..28

    float acc[2][8][4];
    #pragma unroll
    for (int mt = 0; mt < 2; ++mt)
        #pragma unroll
        for (int nt = 0; nt < 8; ++nt)
            #pragma unroll
            for (int i = 0; i < 4; ++i) acc[mt][nt][i] = 0.f;

    float4 pa[4], pb[4];
    // prefetch chunk 0
    #pragma unroll
    for (int i = 0; i < 4; ++i) {
        int r = lr + i * 32;
        pa[i] = *reinterpret_cast<const float4*>(&x[(size_t)(m0 + r) * D_ + lc]);
        pb[i] = *reinterpret_cast<const float4*>(&W[(size_t)(n0 + r) * D_ + lc]);
    }
    // store chunk 0 -> stage 0
    {
        uint32_t* A = smq;
        uint32_t* Bp = smq + 128 * QLA;
        #pragma unroll
        for (int i = 0; i < 4; ++i) {
            int r = lr + i * 32;
            uint4 ta = make_uint4(f2tf32(pa[i].x), f2tf32(pa[i].y),
                                  f2tf32(pa[i].z), f2tf32(pa[i].w));
            *reinterpret_cast<uint4*>(&A[r * QLA + lc]) = ta;
            uint4 tb = make_uint4(f2tf32(pb[i].x), f2tf32(pb[i].y),
                                  f2tf32(pb[i].z), f2tf32(pb[i].w));
            *reinterpret_cast<uint4*>(&Bp[r * QLA + lc]) = tb;
        }
    }
    __syncthreads();

    for (int kc = 0; kc < 32; ++kc) {
        const int s = kc & 1;
        if (kc + 1 < 32) {
            int koff = (kc + 1) * 32;
            #pragma unroll
            for (int i = 0; i < 4; ++i) {
                int r = lr + i * 32;
                pa[i] = *reinterpret_cast<const float4*>(
                    &x[(size_t)(m0 + r) * D_ + koff + lc]);
                pb[i] = *reinterpret_cast<const float4*>(
                    &W[(size_t)(n0 + r) * D_ + koff + lc]);
            }
        }

        const uint32_t* As = smq + s * QSTG;
        const uint32_t* Bs = As + 128 * QLA;
        #pragma unroll
        for (int k8 = 0; k8 < 4; ++k8) {
            int k0 = k8 * 8;
            uint32_t a[2][4];
            #pragma unroll
            for (int mt = 0; mt < 2; ++mt) {
                int r = warpM + mt * 16 + qr;
                a[mt][0] = As[r * QLA + k0 + qc];
                a[mt][1] = As[(r + 8) * QLA + k0 + qc];
                a[mt][2] = As[r * QLA + k0 + qc + 4];
                a[mt][3] = As[(r + 8) * QLA + k0 + qc + 4];
            }
            #pragma unroll
            for (int nt = 0; nt < 8; ++nt) {
                uint32_t b[2];
                int n = warpN + nt * 8 + qr;
                b[0] = Bs[n * QLA + k0 + qc];
                b[1] = Bs[n * QLA + k0 + qc + 4];
                mma_tf32(acc[0][nt], a[0], b, acc[0][nt]);
                mma_tf32(acc[1][nt], a[1], b, acc[1][nt]);
            }
        }

        if (kc + 1 < 32) {
            uint32_t* A = smq + (s ^ 1) * QSTG;
            uint32_t* Bp = A + 128 * QLA;
            #pragma unroll
            for (int i = 0; i < 4; ++i) {
                int r = lr + i * 32;
                uint4 ta = make_uint4(f2tf32(pa[i].x), f2tf32(pa[i].y),
                                      f2tf32(pa[i].z), f2tf32(pa[i].w));
                *reinterpret_cast<uint4*>(&A[r * QLA + lc]) = ta;
                uint4 tb = make_uint4(f2tf32(pb[i].x), f2tf32(pb[i].y),
                                      f2tf32(pb[i].z), f2tf32(pb[i].w));
                *reinterpret_cast<uint4*>(&Bp[r * QLA + lc]) = tb;
            }
        }
        __syncthreads();
    }

    // Epilogue: bias + scatter to [b,h,s,hd]
    #pragma unroll
    for (int mt = 0; mt < 2; ++mt) {
        #pragma unroll
        for (int nt = 0; nt < 8; ++nt) {
            int gn = n0 + warpN + nt * 8 + 2 * qc;   // even
            int head = gn >> 6;
            int hd = gn & 63;
            float b0 = bias[gn], b1 = bias[gn + 1];
            int rA = m0 + warpM + mt * 16 + qr;
            int rB = rA + 8;
            int bbA = rA >> 11, ssA = rA & (S_ - 1);
            int bbB = rB >> 11, ssB = rB & (S_ - 1);
            float2 vA = make_float2(acc[mt][nt][0] + b0, acc[mt][nt][1] + b1);
            float2 vB = make_float2(acc[mt][nt][2] + b0, acc[mt][nt][3] + b1);
            *reinterpret_cast<float2*>(
                &out[(((size_t)bbA * H_ + head) * S_ + ssA) * HD_ + hd]) = vA;
            *reinterpret_cast<float2*>(
                &out[(((size_t)bbB * H_ + head) * S_ + ssB) * HD_ + hd]) = vB;
        }
    }
}

// ===========================================================================
// Kernel 2: flash attention via tf32 mma.sync.
// Block = 128 q-rows of one (b,h); 256 threads = 8 warps; warp w owns q-rows
// [w*16, w*16+16). Key chunks of 64 (halved so P fits a real buffer).
// smem (tf32 words): Qs[128][68] + Ks[64][68] + Vs[64][72] + Ps[128][68]
//   = 26368 words = 105472 B -> 2 CTAs/SM.
// ===========================================================================
#define LQ 68
#define LK 68
#define LVV 72
#define LP 68
#define ATT_SMEM ((size_t)(128 * LQ + 64 * LK + 64 * LVV + 128 * LP) * 4)

__global__ __launch_bounds__(256, 2) void attn_kernel(float* __restrict__ out)
{
    extern __shared__ uint32_t sma[];
    uint32_t* Qs = sma;                       // [128][LQ]  q-major (pre-scaled)
    uint32_t* Ks = Qs + 128 * LQ;             // [64][LK]   key-major
    uint32_t* Vs = Ks + 64 * LK;              // [64][LVV]  key-major
    uint32_t* Ps = Vs + 64 * LVV;             // [128][LP]  q-major

    const int tid  = threadIdx.x;
    const int wid  = tid >> 5;
    const int lane = tid & 31;
    const int qr = lane >> 2;
    const int qc = lane & 3;
    const int wq = wid * 16;                  // warp's q-row base

    const int qBase = blockIdx.x * 128;
    const int bh = blockIdx.y;
    const int b  = bh >> 4;
    const int h  = bh & 15;

    const float* qptr = g_q + (size_t)bh * S_ * HD_;
    const float* kptr = g_k + (size_t)bh * S_ * HD_;
    const float* vptr = g_v + (size_t)bh * S_ * HD_;

    // Load Q tile [128][64], scale 1/sqrt(64), convert tf32
    #pragma unroll
    for (int i = 0; i < 2; ++i) {
        int idx = tid + i * 256;              // 0..511
        int r = idx >> 2;                     // 0..127
        int c = (idx & 3) << 4;               // 0,16,32,48
        #pragma unroll
        for (int u = 0; u < 4; ++u) {
            float4 v = *reinterpret_cast<const float4*>(
                &qptr[(size_t)(qBase + r) * HD_ + c + u * 4]);
            uint4 t = make_uint4(f2tf32(v.x * 0.125f), f2tf32(v.y * 0.125f),
                                 f2tf32(v.z * 0.125f), f2tf32(v.w * 0.125f));
            *reinterpret_cast<uint4*>(&Qs[r * LQ + c + u * 4]) = t;
        }
    }

    float o[8][4];
    #pragma unroll
    for (int nt = 0; nt < 8; ++nt)
        #pragma unroll
        for (int i = 0; i < 4; ++i) o[nt][i] = 0.f;
    float mA = -1e30f, mB = -1e30f, lA = 0.f, lB = 0.f;

    for (int kb = 0; kb < S_; kb += 64) {
        __syncthreads();   // prior QK^T reads of Ks / PV reads of Vs complete
        // Load K and V chunks [64][64] (tf32)
        {
            int idx = tid;                    // 0..255, x4 rows per thread set
            #pragma unroll
            for (int i = 0; i < 4; ++i) {
                int id2 = idx + i * 256;      // 0..1023
                int r = id2 >> 4;             // 0..63
                int c = (id2 & 15) << 2;      // 0..60
                float4 kv = *reinterpret_cast<const float4*>(
                    &kptr[(size_t)(kb + r) * HD_ + c]);
                uint4 tk = make_uint4(f2tf32(kv.x), f2tf32(kv.y),
                                      f2tf32(kv.z), f2tf32(kv.w));
                *reinterpret_cast<uint4*>(&Ks[r * LK + c]) = tk;
                float4 vv = *reinterpret_cast<const float4*>(
                    &vptr[(size_t)(kb + r) * HD_ + c]);
                uint4 tv = make_uint4(f2tf32(vv.x), f2tf32(vv.y),
                                      f2tf32(vv.z), f2tf32(vv.w));
                *reinterpret_cast<uint4*>(&Vs[r * LVV + c]) = tv;
            }
        }
        __syncthreads();

        // S = Q K^T : 1 m-tile x 8 n-tiles per warp, k = 64 (8 steps)
        float s[8][4];
        #pragma unroll
        for (int nt = 0; nt < 8; ++nt)
            #pragma unroll
            for (int i = 0; i < 4; ++i) s[nt][i] = 0.f;

        #pragma unroll 2
        for (int k8 = 0; k8 < 8; ++k8) {
            int k0 = k8 * 8;
            uint32_t a[4];
            a[0] = Qs[(wq + qr) * LQ + k0 + qc];
            a[1] = Qs[(wq + qr + 8) * LQ + k0 + qc];
            a[2] = Qs[(wq + qr) * LQ + k0 + qc + 4];
            a[3] = Qs[(wq + qr + 8) * LQ + k0 + qc + 4];
            #pragma unroll
            for (int nt = 0; nt < 8; ++nt) {
                uint32_t bfr[2];
                bfr[0] = Ks[(nt * 8 + qr) * LK + k0 + qc];
                bfr[1] = Ks[(nt * 8 + qr) * LK + k0 + qc + 4];
                mma_tf32(s[nt], a, bfr, s[nt]);
            }
        }

        // Online softmax on fragments.
        // Row A = wq+qr (regs 0,1), Row B = wq+qr+8 (regs 2,3).
        float mtA = -1e30f, mtB = -1e30f;
        #pragma unroll
        for (int nt = 0; nt < 8; ++nt) {
            mtA = fmaxf(mtA, fmaxf(s[nt][0], s[nt][1]));
            mtB = fmaxf(mtB, fmaxf(s[nt][2], s[nt][3]));
        }
        #pragma unroll
        for (int off = 1; off < 4; off <<= 1) {
            mtA = fmaxf(mtA, __shfl_xor_sync(0xffffffffu, mtA, off));
            mtB = fmaxf(mtB, __shfl_xor_sync(0xffffffffu, mtB, off));
        }
        float mnA = fmaxf(mA, mtA), mnB = fmaxf(mB, mtB);
        float cA = __expf(mA - mnA), cB = __expf(mB - mnB);
        float rsA = 0.f, rsB = 0.f;
        #pragma unroll
        for (int nt = 0; nt < 8; ++nt) {
            s[nt][0] = __expf(s[nt][0] - mnA);
            s[nt][1] = __expf(s[nt][1] - mnA);
            s[nt][2] = __expf(s[nt][2] - mnB);
            s[nt][3] = __expf(s[nt][3] - mnB);
            rsA += s[nt][0] + s[nt][1];
            rsB += s[nt][2] + s[nt][3];
        }
        #pragma unroll
        for (int off = 1; off < 4; off <<= 1) {
            rsA += __shfl_xor_sync(0xffffffffu, rsA, off);
            rsB += __shfl_xor_sync(0xffffffffu, rsB, off);
        }
        lA = lA * cA + rsA;  mA = mnA;
        lB = lB * cB + rsB;  mB = mnB;
        #pragma unroll
        for (int nt = 0; nt < 8; ++nt) {
            o[nt][0] *= cA; o[nt][1] *= cA;
            o[nt][2] *= cB; o[nt][3] *= cB;
        }

        // Store P (tf32) to warp-private Ps rows (cols 0..63 < LP)
        #pragma unroll
        for (int nt = 0; nt < 8; ++nt) {
            uint2 pa = make_uint2(f2tf32(s[nt][0]), f2tf32(s[nt][1]));
            uint2 pb = make_uint2(f2tf32(s[nt][2]), f2tf32(s[nt][3]));
            *reinterpret_cast<uint2*>(&Ps[(wq + qr) * LP + nt * 8 + 2 * qc]) = pa;
            *reinterpret_cast<uint2*>(&Ps[(wq + qr + 8) * LP + nt * 8 + 2 * qc]) = pb;
        }
        __syncwarp();   // warp writes/reads its own 16 Ps rows only

        // O += P V : 1 m-tile x 8 n-tiles, k = 64 (8 steps)
        #pragma unroll 4
        for (int k8 = 0; k8 < 8; ++k8) {
            int k0 = k8 * 8;
            uint32_t a[4];
            a[0] = Ps[(wq + qr) * LP + k0 + qc];
            a[1] = Ps[(wq + qr + 8) * LP + k0 + qc];
            a[2] = Ps[(wq + qr) * LP + k0 + qc + 4];
            a[3] = Ps[(wq + qr + 8) * LP + k0 + qc + 4];
            #pragma unroll
            for (int nt = 0; nt < 8; ++nt) {
                uint32_t bfr[2];
                bfr[0] = Vs[(k0 + qc) * LVV + nt * 8 + qr];
                bfr[1] = Vs[(k0 + qc + 4) * LVV + nt * 8 + qr];
                mma_tf32(o[nt], a, bfr, o[nt]);
            }
        }
    }

    // Epilogue: normalize, write [b,s,h*hd]
    float invA = 1.f / lA, invB = 1.f / lB;
    int rowA = qBase + wq + qr;
    int rowB = rowA + 8;
    #pragma unroll
    for (int nt = 0; nt < 8; ++nt) {
        int col = h * HD_ + nt * 8 + 2 * qc;
        float2 vA = make_float2(o[nt][0] * invA, o[nt][1] * invA);
        float2 vB = make_float2(o[nt][2] * invB, o[nt][3] * invB);
        *reinterpret_cast<float2*>(&out[(size_t)(b * S_ + rowA) * D_ + col]) = vA;
        *reinterpret_cast<float2*>(&out[(size_t)(b * S_ + rowB) * D_ + col]) = vB;
    }
}

// ---------------------------------------------------------------------------
extern "C" void kernel_launch(void* const* d_in, const int* in_sizes, int n_in,
                              void* d_out, int out_size)
{
    const float* x  = (const float*)d_in[0];
    const float* Wq = (const float*)d_in[1];
    const float* bq = (const float*)d_in[2];
    const float* Wk = (const float*)d_in[3];
    const float* bk = (const float*)d_in[4];
    const float* Wv = (const float*)d_in[5];
    const float* bv = (const float*)d_in[6];
    float* out = (float*)d_out;

    cudaFuncSetAttribute(qkv_mma_kernel,
                         cudaFuncAttributeMaxDynamicSharedMemorySize, (int)QKV_SMEM);
    qkv_mma_kernel<<<dim3(24, 64), 256, QKV_SMEM>>>(x, Wq, bq, Wk, bk, Wv, bv);

    cudaFuncSetAttribute(attn_kernel,
                         cudaFuncAttributeMaxDynamicSharedMemorySize, (int)ATT_SMEM);
    attn_kernel<<<dim3(S_ / 128, B_ * H_), 256, ATT_SMEM>>>(out);
}